// round 14
// baseline (speedup 1.0000x reference)
#include <cuda_runtime.h>
#include <cuda_bf16.h>
#include <cuda_fp16.h>
#include <cstdint>

// ---------------- problem constants ----------------
#define HID 128
#define VOCAB 50000
#define N_NODES 741376
// LEVEL_SIZES = {4096,16384,65536,131072,262144,262144}
// OFF         = {0,4096,20480,86016,217088,479232,741376}

// ---------------- device scratch ----------------
__device__ __half g_Bx[2 * 512 * 64];            // [W_ix|W_ox|W_ux|W_fx] fp16, swizzled, 2 k-chunks
__device__ __half g_Bh[2 * 512 * 64];            // [W_ih|W_oh|W_uh|W_fh] fp16, swizzled, 2 k-chunks
__device__ __half g_emb2[(size_t)VOCAB * 256];   // emb hi(128)|lo(128) fp16
__device__ __half g_h2[(size_t)N_NODES * 256];   // h hi|lo fp16
__device__ __half g_hs2[(size_t)131072 * 256];   // h_sum hi|lo fp16
__device__ float g_c[(size_t)N_NODES * 128];
__device__ __half g_XG[(size_t)VOCAB * 512];     // x-gate preacts (fp16)
__device__ __half g_AH[(size_t)262144 * 512];    // h-gate preacts; L=4 ld=512 (cols 384+ = FH)
__device__ __half g_FH[(size_t)262144 * 128];
__device__ float g_bsum[512];                    // [b_ix+b_ih | b_ox+b_oh | b_ux+b_uh | b_fx+b_fh]

// ---------------- PTX helpers (baseline ISA only: sm_80-class) ----------------
__device__ __forceinline__ uint32_t smem_u32(const void* p) {
    uint32_t a;
    asm("{ .reg .u64 t; cvta.to.shared.u64 t, %1; cvt.u32.u64 %0, t; }" : "=r"(a) : "l"(p));
    return a;
}
#define CPA(dst, src, sz) \
    asm volatile("cp.async.cg.shared.global [%0], [%1], 16, %2;" :: "r"(dst), "l"(src), "r"(sz))
#define CPA_COMMIT() asm volatile("cp.async.commit_group;" ::: "memory")
#define CPA_WAIT0() asm volatile("cp.async.wait_group 0;" ::: "memory")

__device__ __forceinline__ void ldsm4(uint32_t* r, uint32_t addr) {
    asm volatile("ldmatrix.sync.aligned.m8n8.x4.shared.b16 {%0,%1,%2,%3}, [%4];"
                 : "=r"(r[0]), "=r"(r[1]), "=r"(r[2]), "=r"(r[3]) : "r"(addr));
}
__device__ __forceinline__ void mma_f16(float* c, const uint32_t* a, const uint32_t* b) {
    asm volatile("mma.sync.aligned.m16n8k16.row.col.f32.f16.f16.f32 "
                 "{%0,%1,%2,%3}, {%4,%5,%6,%7}, {%8,%9}, {%0,%1,%2,%3};"
                 : "+f"(c[0]), "+f"(c[1]), "+f"(c[2]), "+f"(c[3])
                 : "r"(a[0]), "r"(a[1]), "r"(a[2]), "r"(a[3]), "r"(b[0]), "r"(b[1]));
}

// ---------------- math helpers ----------------
__device__ __forceinline__ float sigm(float x) { return 1.0f / (1.0f + __expf(-x)); }
__device__ __forceinline__ float tanh_(float x) {
    float t = __expf(2.0f * x);
    return 1.0f - 2.0f / (t + 1.0f);
}
// pack 4 floats into 4 fp16 (8 bytes)
__device__ __forceinline__ uint2 pack4h(float a, float b, float c, float d) {
    __half2 p0 = __floats2half2_rn(a, b);
    __half2 p1 = __floats2half2_rn(c, d);
    uint2 r;
    r.x = *(uint32_t*)&p0;
    r.y = *(uint32_t*)&p1;
    return r;
}
// load 4 fp16 -> 4 floats
__device__ __forceinline__ void load4h(const __half* p, float* v) {
    uint2 u = *(const uint2*)p;
    float2 f0 = __half22float2(*(__half2*)&u.x);
    float2 f1 = __half22float2(*(__half2*)&u.y);
    v[0] = f0.x; v[1] = f0.y; v[2] = f1.x; v[3] = f1.y;
}
// split-store 4 floats as hi/lo fp16 quads
__device__ __forceinline__ void split_store4(__half* rowbase, int d4, const float* v) {
    float hi[4], lo[4];
#pragma unroll
    for (int j = 0; j < 4; j++) {
        __half h = __float2half_rn(v[j]);
        hi[j] = __half2float(h);
        lo[j] = v[j] - hi[j];
    }
    *(uint2*)(rowbase + d4) = pack4h(hi[0], hi[1], hi[2], hi[3]);
    *(uint2*)(rowbase + 128 + d4) = pack4h(lo[0], lo[1], lo[2], lo[3]);
}

// ---------------- weight packing: 2 swizzled fp16 chunk images ----------------
__global__ void pack_b(const float* __restrict__ Wix, const float* __restrict__ Wox,
                       const float* __restrict__ Wux, const float* __restrict__ Wfx,
                       const float* __restrict__ Wih, const float* __restrict__ Woh,
                       const float* __restrict__ Wuh, const float* __restrict__ Wfh) {
    int idx = blockIdx.x * blockDim.x + threadIdx.x;
    if (idx >= 2 * 512 * 64) return;
    int kc = idx >> 15;
    int rem = idx & 32767;
    int n = rem >> 6;
    int kk = rem & 63;
    int k = (kc << 6) + kk;
    int g = n >> 7, j = n & 127;
    const float* sx = (g == 0) ? Wix : (g == 1) ? Wox : (g == 2) ? Wux : Wfx;
    const float* sh = (g == 0) ? Wih : (g == 1) ? Woh : (g == 2) ? Wuh : Wfh;
    int unit = kk >> 3;
    uint32_t off = (uint32_t)kc * 65536u + (uint32_t)n * 128u +
                   (uint32_t)((unit ^ (n & 7)) << 4) + (uint32_t)((kk & 7) * 2);
    *(__half*)((char*)g_Bx + off) = __float2half_rn(sx[k * 128 + j]);
    *(__half*)((char*)g_Bh + off) = __float2half_rn(sh[k * 128 + j]);
}

__global__ void pack_bias(const float* __restrict__ b_ix, const float* __restrict__ b_ih,
                          const float* __restrict__ b_ox, const float* __restrict__ b_oh,
                          const float* __restrict__ b_ux, const float* __restrict__ b_uh,
                          const float* __restrict__ b_fx, const float* __restrict__ b_fh) {
    int i = threadIdx.x;   // 512
    int g = i >> 7, j = i & 127;
    float v = (g == 0) ? b_ix[j] + b_ih[j] : (g == 1) ? b_ox[j] + b_oh[j]
            : (g == 2) ? b_ux[j] + b_uh[j] : b_fx[j] + b_fh[j];
    g_bsum[i] = v;
}

// emb split: 8 rows/block, 32 threads/row
__global__ void __launch_bounds__(256) emb2_kernel(const float* __restrict__ emb) {
    int t = threadIdx.x, nl = t >> 5, lt = t & 31, d4 = lt * 4;
    long long row = (long long)blockIdx.x * 8 + nl;
    float4 v = *(const float4*)(emb + row * 128 + d4);
    float vv[4] = {v.x, v.y, v.z, v.w};
    split_store4(g_emb2 + row * 256, d4, vv);
}

// ---------------- HMMA fp16 split GEMM: single-shot SMEM, sync-free mainloop ----------------
// C[M, 128*gridDim.y] = A(f32-equiv via fp16 hi|lo)[M,128] @ B[128, ...]
// K=256 as 4 chunks of 64: A images {hi0,hi1,lo0,lo1} (16KB each), B images {0,1} (16KB each).
// All 96KB loaded once via cp.async; one __syncthreads; 16 k-steps of pure ldsm+mma.
__global__ void __launch_bounds__(256) hmma_gemm(const __half* __restrict__ A2,
                                                 const __half* __restrict__ Bpack,
                                                 __half* __restrict__ C,
                                                 int M, int n_start, int ldc) {
    extern __shared__ char smem[];
    const uint32_t sb = smem_u32(smem);
    const int tid = threadIdx.x, lane = tid & 31, wid = tid >> 5;
    const long long m0 = (long long)blockIdx.x * 128;
    const int n0 = blockIdx.y * 128;

    const int q = lane >> 3, r8 = lane & 7;
    const int rowA = ((q & 1) << 3) + r8;
    const int kuA = q >> 1;
    const int rowB = ((q >> 1) << 3) + r8;
    const int kuB = q & 1;
    const int wm = (wid >> 2) << 6;
    const int wn = (wid & 3) << 5;

    static const int offA_[4] = {0, 64, 128, 192};   // hi k0-63, hi k64-127, lo k0-63, lo k64-127

    // ---- load B: 2 images x 1024 units ----
#pragma unroll
    for (int img = 0; img < 2; img++) {
        const char* bsrc = (const char*)Bpack + img * 65536 + (size_t)(n_start + n0) * 128;
        uint32_t bdst = sb + 65536 + (uint32_t)img * 16384;
#pragma unroll
        for (int i = 0; i < 4; i++) {
            int f = tid + i * 256;
            CPA(bdst + (uint32_t)(f * 16), bsrc + f * 16, 16);
        }
    }
    // ---- load A: 4 images x 1024 units (swizzled stores) ----
#pragma unroll
    for (int kc = 0; kc < 4; kc++) {
        uint32_t adst = sb + (uint32_t)kc * 16384;
#pragma unroll
        for (int i = 0; i < 4; i++) {
            int f = tid + i * 256;
            int r = f >> 3, u = f & 7;
            uint32_t dst = adst + (uint32_t)(r * 128 + ((u ^ (r & 7)) << 4));
            const char* src = (const char*)(A2 + (m0 + r) * 256 + offA_[kc]) + u * 16;
            int sz = ((m0 + r) < M) ? 16 : 0;
            CPA(dst, src, sz);
        }
    }
    CPA_COMMIT();
    CPA_WAIT0();
    __syncthreads();

    float acc[4][4][4];
#pragma unroll
    for (int i = 0; i < 4; i++)
#pragma unroll
        for (int j = 0; j < 4; j++)
#pragma unroll
            for (int t = 0; t < 4; t++) acc[i][j][t] = 0.0f;

#pragma unroll
    for (int kc = 0; kc < 4; kc++) {
        const uint32_t aimg = sb + (uint32_t)kc * 16384;
        const uint32_t bimg = sb + 65536 + (uint32_t)(kc & 1) * 16384;
#pragma unroll
        for (int ks = 0; ks < 4; ks++) {
            uint32_t af[16];
#pragma unroll
            for (int mt = 0; mt < 4; mt++) {
                int row = wm + mt * 16 + rowA;
                uint32_t addr = aimg + (uint32_t)((row << 7) + ((((ks << 1) + kuA) ^ r8) << 4));
                ldsm4(&af[mt * 4], addr);
            }
            uint32_t bf[8];
#pragma unroll
            for (int j = 0; j < 2; j++) {
                int row = wn + j * 16 + rowB;
                uint32_t addr = bimg + (uint32_t)((row << 7) + ((((ks << 1) + kuB) ^ r8) << 4));
                ldsm4(&bf[j * 4], addr);
            }
#pragma unroll
            for (int mt = 0; mt < 4; mt++)
#pragma unroll
                for (int ng = 0; ng < 4; ng++)
                    mma_f16(acc[mt][ng], &af[mt * 4], &bf[ng * 2]);
        }
    }

    const int tr = lane >> 2, tc = (lane & 3) * 2;
#pragma unroll
    for (int mt = 0; mt < 4; mt++) {
        long long r0 = m0 + wm + mt * 16 + tr;
#pragma unroll
        for (int ng = 0; ng < 4; ng++) {
            int col = n0 + wn + ng * 8 + tc;
            if (r0 < M) {
                __half2 v = __floats2half2_rn(acc[mt][ng][0], acc[mt][ng][1]);
                *(__half2*)(C + r0 * (long long)ldc + col) = v;
            }
            if (r0 + 8 < M) {
                __half2 v = __floats2half2_rn(acc[mt][ng][2], acc[mt][ng][3]);
                *(__half2*)(C + (r0 + 8) * (long long)ldc + col) = v;
            }
        }
    }
}

// ---------------- leaf level (L=5): 8 nodes/block, 32 thr/node ----------------
__global__ void __launch_bounds__(256) leaf_kernel(const int* __restrict__ sen) {
    int t = threadIdx.x, nl = t >> 5, lt = t & 31, d4 = lt * 4;
    long long node = 479232LL + (long long)blockIdx.x * 8 + nl;
    int v = __ldg(&sen[node]);
    const __half* xg = g_XG + (long long)v * 512;
    float Xi[4], Xo[4], Xu[4];
    load4h(xg + d4, Xi);
    load4h(xg + 128 + d4, Xo);
    load4h(xg + 256 + d4, Xu);
    float4 bi = *(const float4*)(g_bsum + d4);
    float4 bo = *(const float4*)(g_bsum + 128 + d4);
    float4 bu = *(const float4*)(g_bsum + 256 + d4);
    const float* Bi = (const float*)&bi; const float* Bo = (const float*)&bo;
    const float* Bu = (const float*)&bu;
    float cv[4], hv[4];
#pragma unroll
    for (int j = 0; j < 4; j++) {
        float iv = sigm(Xi[j] + Bi[j]);
        float ov = sigm(Xo[j] + Bo[j]);
        float uv = tanh_(Xu[j] + Bu[j]);
        cv[j] = iv * uv;
        hv[j] = ov * tanh_(cv[j]);
    }
    *(float4*)(g_c + node * 128 + d4) = make_float4(cv[0], cv[1], cv[2], cv[3]);
    split_store4(g_h2 + node * 256, d4, hv);
}

// ---------------- combine: 8 nodes/block; writes parent h-sum when wr>0 ----------------
__global__ void __launch_bounds__(256) combine_kernel(const int* __restrict__ sen,
                                                      long long o0, long long c0,
                                                      int ratio, int wr,
                                                      const __half* __restrict__ ahp, int lda,
                                                      const __half* __restrict__ fhp, int ldf) {
    __shared__ float hsm[8][128];
    int t = threadIdx.x, nl = t >> 5, lt = t & 31, d4 = lt * 4;
    long long p = (long long)blockIdx.x * 8 + nl;
    long long node = o0 + p;
    int v = __ldg(&sen[node]);
    const __half* xg = g_XG + (long long)v * 512;
    const __half* ah = ahp + p * (long long)lda;
    float Xi[4], Xo[4], Xu[4], Xf[4], Ai[4], Ao[4], Au[4];
    load4h(xg + d4, Xi);
    load4h(xg + 128 + d4, Xo);
    load4h(xg + 256 + d4, Xu);
    load4h(xg + 384 + d4, Xf);
    load4h(ah + d4, Ai);
    load4h(ah + 128 + d4, Ao);
    load4h(ah + 256 + d4, Au);
    float4 bi = *(const float4*)(g_bsum + d4);
    float4 bo = *(const float4*)(g_bsum + 128 + d4);
    float4 bu = *(const float4*)(g_bsum + 256 + d4);
    float4 bf = *(const float4*)(g_bsum + 384 + d4);
    const float *Bi = (const float*)&bi, *Bo = (const float*)&bo, *Bu = (const float*)&bu,
                *Bf = (const float*)&bf;
    float iv[4], ov[4], uv[4], xfv[4], fcv[4];
#pragma unroll
    for (int j = 0; j < 4; j++) {
        iv[j] = sigm(Xi[j] + Ai[j] + Bi[j]);
        ov[j] = sigm(Xo[j] + Ao[j] + Bo[j]);
        uv[j] = tanh_(Xu[j] + Au[j] + Bu[j]);
        xfv[j] = Xf[j] + Bf[j];
        fcv[j] = 0.0f;
    }
    for (int k = 0; k < ratio; k++) {
        long long ch = p * ratio + k;
        float F[4];
        load4h(fhp + ch * (long long)ldf + d4, F);
        float4 cc = *(const float4*)(g_c + (c0 + ch) * 128 + d4);
        const float* Cc = (const float*)&cc;
#pragma unroll
        for (int j = 0; j < 4; j++) fcv[j] += sigm(xfv[j] + F[j]) * Cc[j];
    }
    float cv[4], hv[4];
#pragma unroll
    for (int j = 0; j < 4; j++) {
        cv[j] = iv[j] * uv[j] + fcv[j];
        hv[j] = ov[j] * tanh_(cv[j]);
    }
    *(float4*)(g_c + node * 128 + d4) = make_float4(cv[0], cv[1], cv[2], cv[3]);
    split_store4(g_h2 + node * 256, d4, hv);

    if (wr) {
        *(float4*)&hsm[nl][d4] = make_float4(hv[0], hv[1], hv[2], hv[3]);
        __syncthreads();
        if ((nl & (wr - 1)) == 0) {
            float s[4];
#pragma unroll
            for (int j = 0; j < 4; j++) s[j] = hv[j];
            for (int q = 1; q < wr; q++) {
                float4 o = *(float4*)&hsm[nl + q][d4];
#pragma unroll
                for (int j = 0; j < 4; j++) s[j] += ((const float*)&o)[j];
            }
            long long prow = p / wr;
            split_store4(g_hs2 + prow * 256, d4, s);
        }
    }
}

// ---------------- output projection ----------------
__global__ void out_kernel(const float* __restrict__ Wout, const float* __restrict__ bout,
                           float* __restrict__ out) {
    int n = blockIdx.x;
    int d = threadIdx.x;
    long long base = (long long)n * 256;
    float hv = __half2float(g_h2[base + d]) + __half2float(g_h2[base + 128 + d]);
    float4 w = *(const float4*)(Wout + d * 4);
    float v0 = hv * w.x, v1 = hv * w.y, v2 = hv * w.z, v3 = hv * w.w;
#pragma unroll
    for (int off = 16; off > 0; off >>= 1) {
        v0 += __shfl_down_sync(0xffffffffu, v0, off);
        v1 += __shfl_down_sync(0xffffffffu, v1, off);
        v2 += __shfl_down_sync(0xffffffffu, v2, off);
        v3 += __shfl_down_sync(0xffffffffu, v3, off);
    }
    __shared__ float s[4][4];
    int warp = d >> 5, lane = d & 31;
    if (lane == 0) { s[warp][0] = v0; s[warp][1] = v1; s[warp][2] = v2; s[warp][3] = v3; }
    __syncthreads();
    if (d < 4) out[n * 4 + d] = s[0][d] + s[1][d] + s[2][d] + s[3][d] + bout[d];
}

// ---------------- launcher ----------------
extern "C" void kernel_launch(void* const* d_in, const int* in_sizes, int n_in,
                              void* d_out, int out_size) {
    const int* sen = (const int*)d_in[0];
    const float* emb = (const float*)d_in[1];
    const float* W_ix = (const float*)d_in[2];  const float* b_ix = (const float*)d_in[3];
    const float* W_ih = (const float*)d_in[4];  const float* b_ih = (const float*)d_in[5];
    const float* W_fx = (const float*)d_in[6];  const float* b_fx = (const float*)d_in[7];
    const float* W_fh = (const float*)d_in[8];  const float* b_fh = (const float*)d_in[9];
    const float* W_ox = (const float*)d_in[10]; const float* b_ox = (const float*)d_in[11];
    const float* W_oh = (const float*)d_in[12]; const float* b_oh = (const float*)d_in[13];
    const float* W_ux = (const float*)d_in[14]; const float* b_ux = (const float*)d_in[15];
    const float* W_uh = (const float*)d_in[16]; const float* b_uh = (const float*)d_in[17];
    const float* W_out = (const float*)d_in[18]; const float* b_out = (const float*)d_in[19];
    float* out = (float*)d_out;

    __half *E2, *H2, *HS2, *Bx, *Bh, *XG, *AH, *FH;
    cudaGetSymbolAddress((void**)&E2, g_emb2);
    cudaGetSymbolAddress((void**)&H2, g_h2);
    cudaGetSymbolAddress((void**)&HS2, g_hs2);
    cudaGetSymbolAddress((void**)&Bx, g_Bx);
    cudaGetSymbolAddress((void**)&Bh, g_Bh);
    cudaGetSymbolAddress((void**)&XG, g_XG);
    cudaGetSymbolAddress((void**)&AH, g_AH);
    cudaGetSymbolAddress((void**)&FH, g_FH);

    cudaFuncSetAttribute(hmma_gemm, cudaFuncAttributeMaxDynamicSharedMemorySize, 98304);

    static const long long OFFS[7] = {0, 4096, 20480, 86016, 217088, 479232, 741376};
    static const int LS[6] = {4096, 16384, 65536, 131072, 262144, 262144};

    pack_b<<<(2 * 512 * 64 + 255) / 256, 256>>>(W_ix, W_ox, W_ux, W_fx, W_ih, W_oh, W_uh, W_fh);
    pack_bias<<<1, 512>>>(b_ix, b_ih, b_ox, b_oh, b_ux, b_uh, b_fx, b_fh);
    emb2_kernel<<<VOCAB / 8, 256>>>(emb);

    // XG = emb @ [W_ix|W_ox|W_ux|W_fx]  (50000 x 512)
    hmma_gemm<<<dim3((VOCAB + 127) / 128, 4), 256, 98304>>>(E2, Bx, XG, VOCAB, 0, 512);

    leaf_kernel<<<262144 / 8, 256>>>(sen);

    for (int L = 4; L >= 0; --L) {
        long long o0 = OFFS[L], c0 = OFFS[L + 1];
        int nL = LS[L], nC = LS[L + 1];
        int ratio = nC / nL;
        int wr = (L > 0) ? LS[L] / LS[L - 1] : 0;   // parent-group size (h-sum co-write)

        if (ratio == 1) {
            // merged: [AH | FH] = h_child @ [W_ih|W_oh|W_uh|W_fh]  (nL x 512)
            hmma_gemm<<<dim3(nL / 128, 4), 256, 98304>>>(H2 + c0 * 256, Bh, AH, nL, 0, 512);
            combine_kernel<<<nL / 8, 256>>>(sen, o0, c0, ratio, wr, AH, 512, AH + 384, 512);
        } else {
            // AH = h_sum @ [W_ih|W_oh|W_uh]  (nL x 384)
            hmma_gemm<<<dim3(nL / 128, 3), 256, 98304>>>(HS2, Bh, AH, nL, 0, 384);
            // FH = h_child @ W_fh            (nC x 128), rows 384.. of the Bh pack
            hmma_gemm<<<dim3(nC / 128, 1), 256, 98304>>>(H2 + c0 * 256, Bh, FH, nC, 384, 128);
            combine_kernel<<<nL / 8, 256>>>(sen, o0, c0, ratio, wr, AH, 384, FH, 128);
        }
    }

    out_kernel<<<4096, 128>>>(W_out, b_out, out);
}

// round 15
// speedup vs baseline: 1.1231x; 1.1231x over previous
#include <cuda_runtime.h>
#include <cuda_bf16.h>
#include <cuda_fp16.h>
#include <cstdint>

// ---------------- problem constants ----------------
#define HID 128
#define VOCAB 50000
#define N_NODES 741376
// LEVEL_SIZES = {4096,16384,65536,131072,262144,262144}
// OFF         = {0,4096,20480,86016,217088,479232,741376}

// ---------------- device scratch ----------------
__device__ __half g_Bx[2 * 512 * 64];            // [W_ix|W_ox|W_ux|W_fx] fp16, swizzled, 2 k-chunks
__device__ __half g_Bh[2 * 512 * 64];            // [W_ih|W_oh|W_uh|W_fh] fp16, swizzled, 2 k-chunks
__device__ __half g_emb2[(size_t)VOCAB * 256];   // emb hi(128)|lo(128) fp16
__device__ __half g_h2[(size_t)N_NODES * 256];   // h hi|lo fp16
__device__ __half g_hs2[(size_t)131072 * 256];   // h_sum hi|lo fp16
__device__ float g_c[(size_t)N_NODES * 128];
__device__ __half g_XG[(size_t)VOCAB * 512];     // x-gate preacts (fp16)
__device__ __half g_AH[(size_t)262144 * 512];    // h-gate preacts; L=4 ld=512 (cols 384+ = FH)
__device__ __half g_FH[(size_t)262144 * 128];
__device__ float g_bsum[512];                    // [b_ix+b_ih | b_ox+b_oh | b_ux+b_uh | b_fx+b_fh]

// ---------------- PTX helpers (baseline ISA only: sm_80-class) ----------------
__device__ __forceinline__ uint32_t smem_u32(const void* p) {
    uint32_t a;
    asm("{ .reg .u64 t; cvta.to.shared.u64 t, %1; cvt.u32.u64 %0, t; }" : "=r"(a) : "l"(p));
    return a;
}
#define CPA(dst, src, sz) \
    asm volatile("cp.async.cg.shared.global [%0], [%1], 16, %2;" :: "r"(dst), "l"(src), "r"(sz))
#define CPA_COMMIT() asm volatile("cp.async.commit_group;" ::: "memory")
#define CPA_WAIT0() asm volatile("cp.async.wait_group 0;" ::: "memory")
#define CPA_WAIT1() asm volatile("cp.async.wait_group 1;" ::: "memory")

__device__ __forceinline__ void ldsm4(uint32_t* r, uint32_t addr) {
    asm volatile("ldmatrix.sync.aligned.m8n8.x4.shared.b16 {%0,%1,%2,%3}, [%4];"
                 : "=r"(r[0]), "=r"(r[1]), "=r"(r[2]), "=r"(r[3]) : "r"(addr));
}
__device__ __forceinline__ void mma_f16(float* c, const uint32_t* a, const uint32_t* b) {
    asm volatile("mma.sync.aligned.m16n8k16.row.col.f32.f16.f16.f32 "
                 "{%0,%1,%2,%3}, {%4,%5,%6,%7}, {%8,%9}, {%0,%1,%2,%3};"
                 : "+f"(c[0]), "+f"(c[1]), "+f"(c[2]), "+f"(c[3])
                 : "r"(a[0]), "r"(a[1]), "r"(a[2]), "r"(a[3]), "r"(b[0]), "r"(b[1]));
}

// ---------------- math helpers ----------------
__device__ __forceinline__ float sigm(float x) { return 1.0f / (1.0f + __expf(-x)); }
__device__ __forceinline__ float tanh_(float x) {
    float t = __expf(2.0f * x);
    return 1.0f - 2.0f / (t + 1.0f);
}
// pack 4 floats into 4 fp16 (8 bytes)
__device__ __forceinline__ uint2 pack4h(float a, float b, float c, float d) {
    __half2 p0 = __floats2half2_rn(a, b);
    __half2 p1 = __floats2half2_rn(c, d);
    uint2 r;
    r.x = *(uint32_t*)&p0;
    r.y = *(uint32_t*)&p1;
    return r;
}
// load 4 fp16 -> 4 floats
__device__ __forceinline__ void load4h(const __half* p, float* v) {
    uint2 u = *(const uint2*)p;
    float2 f0 = __half22float2(*(__half2*)&u.x);
    float2 f1 = __half22float2(*(__half2*)&u.y);
    v[0] = f0.x; v[1] = f0.y; v[2] = f1.x; v[3] = f1.y;
}
// split-store 4 floats as hi/lo fp16 quads
__device__ __forceinline__ void split_store4(__half* rowbase, int d4, const float* v) {
    float hi[4], lo[4];
#pragma unroll
    for (int j = 0; j < 4; j++) {
        __half h = __float2half_rn(v[j]);
        hi[j] = __half2float(h);
        lo[j] = v[j] - hi[j];
    }
    *(uint2*)(rowbase + d4) = pack4h(hi[0], hi[1], hi[2], hi[3]);
    *(uint2*)(rowbase + 128 + d4) = pack4h(lo[0], lo[1], lo[2], lo[3]);
}

// ---------------- weight packing: 2 swizzled fp16 chunk images ----------------
__global__ void pack_b(const float* __restrict__ Wix, const float* __restrict__ Wox,
                       const float* __restrict__ Wux, const float* __restrict__ Wfx,
                       const float* __restrict__ Wih, const float* __restrict__ Woh,
                       const float* __restrict__ Wuh, const float* __restrict__ Wfh) {
    int idx = blockIdx.x * blockDim.x + threadIdx.x;
    if (idx >= 2 * 512 * 64) return;
    int kc = idx >> 15;
    int rem = idx & 32767;
    int n = rem >> 6;
    int kk = rem & 63;
    int k = (kc << 6) + kk;
    int g = n >> 7, j = n & 127;
    const float* sx = (g == 0) ? Wix : (g == 1) ? Wox : (g == 2) ? Wux : Wfx;
    const float* sh = (g == 0) ? Wih : (g == 1) ? Woh : (g == 2) ? Wuh : Wfh;
    int unit = kk >> 3;
    uint32_t off = (uint32_t)kc * 65536u + (uint32_t)n * 128u +
                   (uint32_t)((unit ^ (n & 7)) << 4) + (uint32_t)((kk & 7) * 2);
    *(__half*)((char*)g_Bx + off) = __float2half_rn(sx[k * 128 + j]);
    *(__half*)((char*)g_Bh + off) = __float2half_rn(sh[k * 128 + j]);
}

__global__ void pack_bias(const float* __restrict__ b_ix, const float* __restrict__ b_ih,
                          const float* __restrict__ b_ox, const float* __restrict__ b_oh,
                          const float* __restrict__ b_ux, const float* __restrict__ b_uh,
                          const float* __restrict__ b_fx, const float* __restrict__ b_fh) {
    int i = threadIdx.x;   // 512
    int g = i >> 7, j = i & 127;
    float v = (g == 0) ? b_ix[j] + b_ih[j] : (g == 1) ? b_ox[j] + b_oh[j]
            : (g == 2) ? b_ux[j] + b_uh[j] : b_fx[j] + b_fh[j];
    g_bsum[i] = v;
}

// emb split: 8 rows/block, 32 threads/row
__global__ void __launch_bounds__(256) emb2_kernel(const float* __restrict__ emb) {
    int t = threadIdx.x, nl = t >> 5, lt = t & 31, d4 = lt * 4;
    long long row = (long long)blockIdx.x * 8 + nl;
    float4 v = *(const float4*)(emb + row * 128 + d4);
    float vv[4] = {v.x, v.y, v.z, v.w};
    split_store4(g_emb2 + row * 256, d4, vv);
}

// ---------------- HMMA fp16 split GEMM: double-buffered A, resident B ----------------
// C[M, 128*gridDim.y] = A(f32-equiv via fp16 hi|lo)[M,128] @ B[128, ...]
// K=256 as 4 chunks of 64: A cols {hi0,hi1,lo0,lo1}; B images {0,1} loaded ONCE.
__global__ void __launch_bounds__(256) hmma_gemm(const __half* __restrict__ A2,
                                                 const __half* __restrict__ Bpack,
                                                 __half* __restrict__ C,
                                                 int M, int n_start, int ldc) {
    extern __shared__ char smem[];
    const uint32_t sb = smem_u32(smem);
    const int tid = threadIdx.x, lane = tid & 31, wid = tid >> 5;
    const long long m0 = (long long)blockIdx.x * 128;
    const int n0 = blockIdx.y * 128;

    const uint32_t sA[2] = {sb, sb + 16384};
    const uint32_t sB[2] = {sb + 32768, sb + 49152};

    const int q = lane >> 3, r8 = lane & 7;
    const int rowA = ((q & 1) << 3) + r8;
    const int kuA = q >> 1;
    const int rowB = ((q >> 1) << 3) + r8;
    const int kuB = q & 1;
    const int wm = (wid >> 2) << 6;
    const int wn = (wid & 3) << 5;

    float acc[4][4][4];
#pragma unroll
    for (int i = 0; i < 4; i++)
#pragma unroll
        for (int j = 0; j < 4; j++)
#pragma unroll
            for (int t = 0; t < 4; t++) acc[i][j][t] = 0.0f;

    static const int offA_[4] = {0, 64, 128, 192};   // hi k0-63, hi k64-127, lo k0-63, lo k64-127

    // A chunk kc -> buffer kc&1
    auto issueA = [&](int kc) {
        const int b = kc & 1;
#pragma unroll
        for (int i = 0; i < 4; i++) {
            int f = tid + i * 256;
            int r = f >> 3, u = f & 7;
            uint32_t dst = sA[b] + (uint32_t)(r * 128 + ((u ^ (r & 7)) << 4));
            const char* src = (const char*)(A2 + (m0 + r) * 256 + offA_[kc]) + u * 16;
            int sz = ((m0 + r) < M) ? 16 : 0;
            CPA(dst, src, sz);
        }
    };

    // group0: both B images (resident) + A chunk0
#pragma unroll
    for (int img = 0; img < 2; img++) {
        const char* bsrc = (const char*)Bpack + img * 65536 + (size_t)(n_start + n0) * 128;
#pragma unroll
        for (int i = 0; i < 4; i++) {
            int f = tid + i * 256;
            CPA(sB[img] + (uint32_t)(f * 16), bsrc + f * 16, 16);
        }
    }
    issueA(0);
    CPA_COMMIT();
    issueA(1);
    CPA_COMMIT();

    for (int kc = 0; kc < 4; kc++) {
        const int b = kc & 1;
        if (kc < 2) {
            CPA_WAIT1();        // kc=0: group0 (B+A0) done; kc=1: group1 (A1) done
        } else if (kc == 2) {
            CPA_WAIT1();        // A2 done
        } else {
            CPA_WAIT0();        // A3 done
        }
        __syncthreads();

        const uint32_t aimg = sA[b];
        const uint32_t bimg = sB[kc & 1];
#pragma unroll
        for (int ks = 0; ks < 4; ks++) {
            uint32_t af[16];
#pragma unroll
            for (int mt = 0; mt < 4; mt++) {
                int row = wm + mt * 16 + rowA;
                uint32_t addr = aimg + (uint32_t)((row << 7) + ((((ks << 1) + kuA) ^ r8) << 4));
                ldsm4(&af[mt * 4], addr);
            }
            uint32_t bf[8];
#pragma unroll
            for (int j = 0; j < 2; j++) {
                int row = wn + j * 16 + rowB;
                uint32_t addr = bimg + (uint32_t)((row << 7) + ((((ks << 1) + kuB) ^ r8) << 4));
                ldsm4(&bf[j * 4], addr);
            }
#pragma unroll
            for (int mt = 0; mt < 4; mt++)
#pragma unroll
                for (int ng = 0; ng < 4; ng++)
                    mma_f16(acc[mt][ng], &af[mt * 4], &bf[ng * 2]);
        }
        __syncthreads();
        if (kc < 2) { issueA(kc + 2); CPA_COMMIT(); }   // refill buffer just freed
    }

    const int tr = lane >> 2, tc = (lane & 3) * 2;
#pragma unroll
    for (int mt = 0; mt < 4; mt++) {
        long long r0 = m0 + wm + mt * 16 + tr;
#pragma unroll
        for (int ng = 0; ng < 4; ng++) {
            int col = n0 + wn + ng * 8 + tc;
            if (r0 < M) {
                __half2 v = __floats2half2_rn(acc[mt][ng][0], acc[mt][ng][1]);
                *(__half2*)(C + r0 * (long long)ldc + col) = v;
            }
            if (r0 + 8 < M) {
                __half2 v = __floats2half2_rn(acc[mt][ng][2], acc[mt][ng][3]);
                *(__half2*)(C + (r0 + 8) * (long long)ldc + col) = v;
            }
        }
    }
}

// ---------------- leaf level (L=5): 8 nodes/block, 32 thr/node ----------------
__global__ void __launch_bounds__(256) leaf_kernel(const int* __restrict__ sen) {
    int t = threadIdx.x, nl = t >> 5, lt = t & 31, d4 = lt * 4;
    long long node = 479232LL + (long long)blockIdx.x * 8 + nl;
    int v = __ldg(&sen[node]);
    const __half* xg = g_XG + (long long)v * 512;
    float Xi[4], Xo[4], Xu[4];
    load4h(xg + d4, Xi);
    load4h(xg + 128 + d4, Xo);
    load4h(xg + 256 + d4, Xu);
    float4 bi = *(const float4*)(g_bsum + d4);
    float4 bo = *(const float4*)(g_bsum + 128 + d4);
    float4 bu = *(const float4*)(g_bsum + 256 + d4);
    const float* Bi = (const float*)&bi; const float* Bo = (const float*)&bo;
    const float* Bu = (const float*)&bu;
    float cv[4], hv[4];
#pragma unroll
    for (int j = 0; j < 4; j++) {
        float iv = sigm(Xi[j] + Bi[j]);
        float ov = sigm(Xo[j] + Bo[j]);
        float uv = tanh_(Xu[j] + Bu[j]);
        cv[j] = iv * uv;
        hv[j] = ov * tanh_(cv[j]);
    }
    *(float4*)(g_c + node * 128 + d4) = make_float4(cv[0], cv[1], cv[2], cv[3]);
    split_store4(g_h2 + node * 256, d4, hv);
}

// ---------------- combine: 8 nodes/block; writes parent h-sum when wr>0 ----------------
__global__ void __launch_bounds__(256) combine_kernel(const int* __restrict__ sen,
                                                      long long o0, long long c0,
                                                      int ratio, int wr,
                                                      const __half* __restrict__ ahp, int lda,
                                                      const __half* __restrict__ fhp, int ldf) {
    __shared__ float hsm[8][128];
    int t = threadIdx.x, nl = t >> 5, lt = t & 31, d4 = lt * 4;
    long long p = (long long)blockIdx.x * 8 + nl;
    long long node = o0 + p;
    int v = __ldg(&sen[node]);
    const __half* xg = g_XG + (long long)v * 512;
    const __half* ah = ahp + p * (long long)lda;
    float Xi[4], Xo[4], Xu[4], Xf[4], Ai[4], Ao[4], Au[4];
    load4h(xg + d4, Xi);
    load4h(xg + 128 + d4, Xo);
    load4h(xg + 256 + d4, Xu);
    load4h(xg + 384 + d4, Xf);
    load4h(ah + d4, Ai);
    load4h(ah + 128 + d4, Ao);
    load4h(ah + 256 + d4, Au);
    float4 bi = *(const float4*)(g_bsum + d4);
    float4 bo = *(const float4*)(g_bsum + 128 + d4);
    float4 bu = *(const float4*)(g_bsum + 256 + d4);
    float4 bf = *(const float4*)(g_bsum + 384 + d4);
    const float *Bi = (const float*)&bi, *Bo = (const float*)&bo, *Bu = (const float*)&bu,
                *Bf = (const float*)&bf;
    float iv[4], ov[4], uv[4], xfv[4], fcv[4];
#pragma unroll
    for (int j = 0; j < 4; j++) {
        iv[j] = sigm(Xi[j] + Ai[j] + Bi[j]);
        ov[j] = sigm(Xo[j] + Ao[j] + Bo[j]);
        uv[j] = tanh_(Xu[j] + Au[j] + Bu[j]);
        xfv[j] = Xf[j] + Bf[j];
        fcv[j] = 0.0f;
    }
    for (int k = 0; k < ratio; k++) {
        long long ch = p * ratio + k;
        float F[4];
        load4h(fhp + ch * (long long)ldf + d4, F);
        float4 cc = *(const float4*)(g_c + (c0 + ch) * 128 + d4);
        const float* Cc = (const float*)&cc;
#pragma unroll
        for (int j = 0; j < 4; j++) fcv[j] += sigm(xfv[j] + F[j]) * Cc[j];
    }
    float cv[4], hv[4];
#pragma unroll
    for (int j = 0; j < 4; j++) {
        cv[j] = iv[j] * uv[j] + fcv[j];
        hv[j] = ov[j] * tanh_(cv[j]);
    }
    *(float4*)(g_c + node * 128 + d4) = make_float4(cv[0], cv[1], cv[2], cv[3]);
    split_store4(g_h2 + node * 256, d4, hv);

    if (wr) {
        *(float4*)&hsm[nl][d4] = make_float4(hv[0], hv[1], hv[2], hv[3]);
        __syncthreads();
        if ((nl & (wr - 1)) == 0) {
            float s[4];
#pragma unroll
            for (int j = 0; j < 4; j++) s[j] = hv[j];
            for (int q = 1; q < wr; q++) {
                float4 o = *(float4*)&hsm[nl + q][d4];
#pragma unroll
                for (int j = 0; j < 4; j++) s[j] += ((const float*)&o)[j];
            }
            long long prow = p / wr;
            split_store4(g_hs2 + prow * 256, d4, s);
        }
    }
}

// ---------------- output projection ----------------
__global__ void out_kernel(const float* __restrict__ Wout, const float* __restrict__ bout,
                           float* __restrict__ out) {
    int n = blockIdx.x;
    int d = threadIdx.x;
    long long base = (long long)n * 256;
    float hv = __half2float(g_h2[base + d]) + __half2float(g_h2[base + 128 + d]);
    float4 w = *(const float4*)(Wout + d * 4);
    float v0 = hv * w.x, v1 = hv * w.y, v2 = hv * w.z, v3 = hv * w.w;
#pragma unroll
    for (int off = 16; off > 0; off >>= 1) {
        v0 += __shfl_down_sync(0xffffffffu, v0, off);
        v1 += __shfl_down_sync(0xffffffffu, v1, off);
        v2 += __shfl_down_sync(0xffffffffu, v2, off);
        v3 += __shfl_down_sync(0xffffffffu, v3, off);
    }
    __shared__ float s[4][4];
    int warp = d >> 5, lane = d & 31;
    if (lane == 0) { s[warp][0] = v0; s[warp][1] = v1; s[warp][2] = v2; s[warp][3] = v3; }
    __syncthreads();
    if (d < 4) out[n * 4 + d] = s[0][d] + s[1][d] + s[2][d] + s[3][d] + bout[d];
}

// ---------------- launcher ----------------
extern "C" void kernel_launch(void* const* d_in, const int* in_sizes, int n_in,
                              void* d_out, int out_size) {
    const int* sen = (const int*)d_in[0];
    const float* emb = (const float*)d_in[1];
    const float* W_ix = (const float*)d_in[2];  const float* b_ix = (const float*)d_in[3];
    const float* W_ih = (const float*)d_in[4];  const float* b_ih = (const float*)d_in[5];
    const float* W_fx = (const float*)d_in[6];  const float* b_fx = (const float*)d_in[7];
    const float* W_fh = (const float*)d_in[8];  const float* b_fh = (const float*)d_in[9];
    const float* W_ox = (const float*)d_in[10]; const float* b_ox = (const float*)d_in[11];
    const float* W_oh = (const float*)d_in[12]; const float* b_oh = (const float*)d_in[13];
    const float* W_ux = (const float*)d_in[14]; const float* b_ux = (const float*)d_in[15];
    const float* W_uh = (const float*)d_in[16]; const float* b_uh = (const float*)d_in[17];
    const float* W_out = (const float*)d_in[18]; const float* b_out = (const float*)d_in[19];
    float* out = (float*)d_out;

    __half *E2, *H2, *HS2, *Bx, *Bh, *XG, *AH, *FH;
    cudaGetSymbolAddress((void**)&E2, g_emb2);
    cudaGetSymbolAddress((void**)&H2, g_h2);
    cudaGetSymbolAddress((void**)&HS2, g_hs2);
    cudaGetSymbolAddress((void**)&Bx, g_Bx);
    cudaGetSymbolAddress((void**)&Bh, g_Bh);
    cudaGetSymbolAddress((void**)&XG, g_XG);
    cudaGetSymbolAddress((void**)&AH, g_AH);
    cudaGetSymbolAddress((void**)&FH, g_FH);

    cudaFuncSetAttribute(hmma_gemm, cudaFuncAttributeMaxDynamicSharedMemorySize, 65536);

    static const long long OFFS[7] = {0, 4096, 20480, 86016, 217088, 479232, 741376};
    static const int LS[6] = {4096, 16384, 65536, 131072, 262144, 262144};

    pack_b<<<(2 * 512 * 64 + 255) / 256, 256>>>(W_ix, W_ox, W_ux, W_fx, W_ih, W_oh, W_uh, W_fh);
    pack_bias<<<1, 512>>>(b_ix, b_ih, b_ox, b_oh, b_ux, b_uh, b_fx, b_fh);
    emb2_kernel<<<VOCAB / 8, 256>>>(emb);

    // XG = emb @ [W_ix|W_ox|W_ux|W_fx]  (50000 x 512)
    hmma_gemm<<<dim3((VOCAB + 127) / 128, 4), 256, 65536>>>(E2, Bx, XG, VOCAB, 0, 512);

    leaf_kernel<<<262144 / 8, 256>>>(sen);

    for (int L = 4; L >= 0; --L) {
        long long o0 = OFFS[L], c0 = OFFS[L + 1];
        int nL = LS[L], nC = LS[L + 1];
        int ratio = nC / nL;
        int wr = (L > 0) ? LS[L] / LS[L - 1] : 0;   // parent-group size (h-sum co-write)

        if (ratio == 1) {
            // merged: [AH | FH] = h_child @ [W_ih|W_oh|W_uh|W_fh]  (nL x 512)
            hmma_gemm<<<dim3(nL / 128, 4), 256, 65536>>>(H2 + c0 * 256, Bh, AH, nL, 0, 512);
            combine_kernel<<<nL / 8, 256>>>(sen, o0, c0, ratio, wr, AH, 512, AH + 384, 512);
        } else {
            // AH = h_sum @ [W_ih|W_oh|W_uh]  (nL x 384)
            hmma_gemm<<<dim3(nL / 128, 3), 256, 65536>>>(HS2, Bh, AH, nL, 0, 384);
            // FH = h_child @ W_fh            (nC x 128), rows 384.. of the Bh pack
            hmma_gemm<<<dim3(nC / 128, 1), 256, 65536>>>(H2 + c0 * 256, Bh, FH, nC, 384, 128);
            combine_kernel<<<nL / 8, 256>>>(sen, o0, c0, ratio, wr, AH, 384, FH, 128);
        }
    }

    out_kernel<<<4096, 128>>>(W_out, b_out, out);
}